// round 13
// baseline (speedup 1.0000x reference)
#include <cuda_runtime.h>
#include <math.h>

#define NHEADS 16
#define NSEQ   2048
#define CDIM   1024
#define HD     64
#define D2     128

// ---------------- scratch ----------------
__device__ float g_x[(size_t)NSEQ * CDIM];
__device__ float g_wp[(size_t)CDIM * 2 * CDIM];
__device__ float g_qkv[(size_t)NSEQ * 6 * CDIM];
__device__ float g_q[(size_t)NHEADS * NSEQ * D2];
__device__ float g_k[(size_t)NHEADS * NSEQ * D2];
__device__ float g_v[(size_t)NHEADS * NSEQ * D2];
__device__ float g_E1[(size_t)NHEADS * NSEQ * NSEQ];   // exp(s1/8)
__device__ float g_E2[(size_t)NHEADS * NSEQ * NSEQ];   // exp(s2/8)
__device__ float g_l1[(size_t)NHEADS * NSEQ];          // row sums
__device__ float g_l2[(size_t)NHEADS * NSEQ];
__device__ float g_out2d[(size_t)NSEQ * 2 * CDIM];
__device__ float g_lam;
__device__ int   g_use;

// ---------------- tf32 / cp.async helpers ----------------
__device__ __forceinline__ unsigned f2tf(float f) {
    unsigned r;
    asm("cvt.rna.tf32.f32 %0, %1;" : "=r"(r) : "f"(f));
    return r;
}

__device__ __forceinline__ void cp16(float* smem, const float* gmem) {
    unsigned s = (unsigned)__cvta_generic_to_shared(smem);
    asm volatile("cp.async.ca.shared.global [%0], [%1], 16;" :: "r"(s), "l"(gmem));
}
#define CP_COMMIT() asm volatile("cp.async.commit_group;")
#define CP_WAIT1()  asm volatile("cp.async.wait_group 1;")
#define CP_WAIT0()  asm volatile("cp.async.wait_group 0;")

#define MMA_TF32(d, a, b)                                                      \
    asm volatile(                                                              \
        "mma.sync.aligned.m16n8k8.row.col.f32.tf32.tf32.f32 "                  \
        "{%0,%1,%2,%3}, {%4,%5,%6,%7}, {%8,%9}, {%0,%1,%2,%3};"                \
        : "+f"((d)[0]), "+f"((d)[1]), "+f"((d)[2]), "+f"((d)[3])               \
        : "r"((a)[0]), "r"((a)[1]), "r"((a)[2]), "r"((a)[3]),                  \
          "r"((b)[0]), "r"((b)[1]))

// NT k-chunk on raw-fp32 smem (stride 36); cvt at gather. 16 MMAs.
#define NT_KCHUNK_F(acc, Af, Bf, kc)                                           \
    do {                                                                       \
        unsigned a_[2][4], b_[8][2];                                           \
        _Pragma("unroll")                                                      \
        for (int mt = 0; mt < 2; mt++) {                                       \
            int m_ = wm * 32 + mt * 16;                                        \
            a_[mt][0] = f2tf((Af)[(m_ + g) * 36 + (kc)*8 + tig]);              \
            a_[mt][1] = f2tf((Af)[(m_ + g + 8) * 36 + (kc)*8 + tig]);          \
            a_[mt][2] = f2tf((Af)[(m_ + g) * 36 + (kc)*8 + tig + 4]);          \
            a_[mt][3] = f2tf((Af)[(m_ + g + 8) * 36 + (kc)*8 + tig + 4]);      \
        }                                                                      \
        _Pragma("unroll")                                                      \
        for (int nt = 0; nt < 8; nt++) {                                       \
            int n_ = wn * 64 + nt * 8 + g;                                     \
            b_[nt][0] = f2tf((Bf)[n_ * 36 + (kc)*8 + tig]);                    \
            b_[nt][1] = f2tf((Bf)[n_ * 36 + (kc)*8 + tig + 4]);                \
        }                                                                      \
        _Pragma("unroll")                                                      \
        for (int mt = 0; mt < 2; mt++)                                         \
            _Pragma("unroll")                                                  \
            for (int nt = 0; nt < 8; nt++)                                     \
                MMA_TF32((acc)[mt][nt], a_[mt], b_[nt]);                       \
    } while (0)

// ---------------- input disambiguation (verbatim, validated) ----------------
__global__ void detect_kernel(const float* __restrict__ bigA, const float* __restrict__ bigB) {
    __shared__ float sa[256], sb[256];
    int t = threadIdx.x;
    float a = 0.f, b = 0.f;
    for (int i = t; i < 4096; i += 256) { a += fabsf(bigA[i]); b += fabsf(bigB[i]); }
    sa[t] = a; sb[t] = b;
    __syncthreads();
    for (int s = 128; s > 0; s >>= 1) {
        if (t < s) { sa[t] += sa[t + s]; sb[t] += sb[t + s]; }
        __syncthreads();
    }
    if (t == 0) g_use = (sb[0] > sa[0]) ? 1 : 0;
}

__global__ void route_kernel(const float* __restrict__ bigA, const float* __restrict__ bigB) {
    int u = g_use;
    const float* px = u ? bigB : bigA;
    const float* pw = u ? bigA : bigB;
    size_t n = (size_t)NSEQ * CDIM;
    for (size_t i = (size_t)blockIdx.x * blockDim.x + threadIdx.x; i < n;
         i += (size_t)gridDim.x * blockDim.x) {
        g_x[i]  = px[i];
        g_wp[i] = pw[i];
    }
}

__global__ void lam_kernel(const float* __restrict__ s0, const float* __restrict__ s1,
                           const float* __restrict__ s2, const float* __restrict__ s3) {
    __shared__ float sa[64], sb[64];
    int t = threadIdx.x;
    sa[t] = s0[t] * s2[t];
    sb[t] = s1[t] * s3[t];
    __syncthreads();
    for (int s = 32; s > 0; s >>= 1) {
        if (t < s) { sa[t] += sa[t + s]; sb[t] += sb[t + s]; }
        __syncthreads();
    }
    if (t == 0) g_lam = expf(sa[0]) - expf(sb[0]) + 0.2f;
}

__global__ void zero_l() {
    int i = blockIdx.x * blockDim.x + threadIdx.x;
    g_l1[i] = 0.f;
    g_l2[i] = 0.f;
}

// ---------------- 1. qkv: NT tf32, cp.async double-buffered ----------------
__global__ void __launch_bounds__(256, 2) qkv_mma(const float* __restrict__ Wqkv) {
    extern __shared__ float sm[];
    float* Asb[2] = { sm,        sm + 4608 };
    float* Bsb[2] = { sm + 9216, sm + 13824 };
    int tid = threadIdx.x, lane = tid & 31, warp = tid >> 5;
    int g = lane >> 2, tig = lane & 3;
    int wm = warp >> 1, wn = warp & 1;
    int n0 = blockIdx.y * 128, d0 = blockIdx.x * 128;

    #pragma unroll
    for (int p = 0; p < 4; p++) {            // stage buf 0, kt=0
        int r = (tid >> 3) + p * 32, c = (tid & 7) * 4;
        cp16(Asb[0] + r * 36 + c, &g_x[(size_t)(n0 + r) * CDIM + c]);
        cp16(Bsb[0] + r * 36 + c, &Wqkv[(size_t)(d0 + r) * CDIM + c]);
    }
    CP_COMMIT();

    float acc[2][8][4] = {};
    const int NIT = CDIM / 32;
    for (int i = 0; i < NIT; i++) {
        if (i + 1 < NIT) {
            int kt = (i + 1) * 32, buf = (i + 1) & 1;
            #pragma unroll
            for (int p = 0; p < 4; p++) {
                int r = (tid >> 3) + p * 32, c = (tid & 7) * 4;
                cp16(Asb[buf] + r * 36 + c, &g_x[(size_t)(n0 + r) * CDIM + kt + c]);
                cp16(Bsb[buf] + r * 36 + c, &Wqkv[(size_t)(d0 + r) * CDIM + kt + c]);
            }
            CP_COMMIT();
            CP_WAIT1();
        } else {
            CP_WAIT0();
        }
        __syncthreads();
        const float* A = Asb[i & 1];
        const float* B = Bsb[i & 1];
        #pragma unroll
        for (int kc = 0; kc < 4; kc++) NT_KCHUNK_F(acc, A, B, kc);
        __syncthreads();
    }
    #pragma unroll
    for (int mt = 0; mt < 2; mt++)
        #pragma unroll
        for (int nt = 0; nt < 8; nt++) {
            int row = n0 + wm * 32 + mt * 16 + g;
            int col = d0 + wn * 64 + nt * 8 + 2 * tig;
            *(float2*)&g_qkv[(size_t)row * (6*CDIM) + col] = make_float2(acc[mt][nt][0], acc[mt][nt][1]);
            *(float2*)&g_qkv[(size_t)(row + 8) * (6*CDIM) + col] = make_float2(acc[mt][nt][2], acc[mt][nt][3]);
        }
}

// ---------------- 2. reorg + RoPE (verbatim, validated) ----------------
__global__ void __launch_bounds__(64) rope_naive() {
    int n = blockIdx.x;
    int h = blockIdx.y;
    int e = threadIdx.x;
    const float* row = g_qkv + (size_t)n * (6 * CDIM);
    int base = h * HD + e;
    float qa = row[0 * CDIM + base];
    float qb = row[1 * CDIM + base];
    float ka = row[2 * CDIM + base];
    float kb = row[3 * CDIM + base];
    float va = row[4 * CDIM + base];
    float vb = row[5 * CDIM + base];

    double invf = exp(-(double)e * (9.210340371976184 / 64.0));
    double th = (double)n * invf;
    float c = (float)cos(th);
    float s = (float)sin(th);

    size_t o = ((size_t)h * NSEQ + n) * D2;
    g_q[o + e]      = qa * c - qb * s;
    g_q[o + 64 + e] = qb * c + qa * s;
    g_k[o + e]      = ka * c - kb * s;
    g_k[o + 64 + e] = kb * c + ka * s;
    g_v[o + e]      = va;
    g_v[o + 64 + e] = vb;
}

// ---------------- 3. scores+exp: cp.async double-buffered, K=64 ----------------
__global__ void __launch_bounds__(256, 2) scores_exp() {
    extern __shared__ float sm[];
    float* Asb[2] = { sm,        sm + 4608 };
    float* Bsb[2] = { sm + 9216, sm + 13824 };
    int tid = threadIdx.x, lane = tid & 31, warp = tid >> 5;
    int g = lane >> 2, tig = lane & 3;
    int wm = warp >> 1, wn = warp & 1;
    int z = blockIdx.z, h = z >> 1, half = z & 1;
    int q0 = blockIdx.y * 128, k0 = blockIdx.x * 128;

    const float* A = g_q + (size_t)h * NSEQ * D2 + half * 64;
    const float* B = g_k + (size_t)h * NSEQ * D2 + half * 64;
    float* E = (half ? g_E2 : g_E1) + (size_t)h * NSEQ * NSEQ;
    float* L = (half ? g_l2 : g_l1) + (size_t)h * NSEQ;

    #pragma unroll
    for (int p = 0; p < 4; p++) {
        int r = (tid >> 3) + p * 32, c = (tid & 7) * 4;
        cp16(Asb[0] + r * 36 + c, &A[(size_t)(q0 + r) * D2 + c]);
        cp16(Bsb[0] + r * 36 + c, &B[(size_t)(k0 + r) * D2 + c]);
    }
    CP_COMMIT();

    float acc[2][8][4] = {};
    #pragma unroll
    for (int i = 0; i < 2; i++) {
        if (i == 0) {
            #pragma unroll
            for (int p = 0; p < 4; p++) {
                int r = (tid >> 3) + p * 32, c = (tid & 7) * 4;
                cp16(Asb[1] + r * 36 + c, &A[(size_t)(q0 + r) * D2 + 32 + c]);
                cp16(Bsb[1] + r * 36 + c, &B[(size_t)(k0 + r) * D2 + 32 + c]);
            }
            CP_COMMIT();
            CP_WAIT1();
        } else {
            CP_WAIT0();
        }
        __syncthreads();
        const float* Af = Asb[i];
        const float* Bf = Bsb[i];
        #pragma unroll
        for (int kc = 0; kc < 4; kc++) NT_KCHUNK_F(acc, Af, Bf, kc);
        __syncthreads();
    }

    float part[2][2] = {{0.f,0.f},{0.f,0.f}};
    #pragma unroll
    for (int mt = 0; mt < 2; mt++)
        #pragma unroll
        for (int nt = 0; nt < 8; nt++) {
            int row = q0 + wm * 32 + mt * 16 + g;
            int col = k0 + wn * 64 + nt * 8 + 2 * tig;
            float e0 = __expf(acc[mt][nt][0] * 0.125f);
            float e1 = __expf(acc[mt][nt][1] * 0.125f);
            float e2 = __expf(acc[mt][nt][2] * 0.125f);
            float e3 = __expf(acc[mt][nt][3] * 0.125f);
            *(float2*)&E[(size_t)row * NSEQ + col] = make_float2(e0, e1);
            *(float2*)&E[(size_t)(row + 8) * NSEQ + col] = make_float2(e2, e3);
            part[mt][0] += e0 + e1;
            part[mt][1] += e2 + e3;
        }
    #pragma unroll
    for (int mt = 0; mt < 2; mt++)
        #pragma unroll
        for (int s = 0; s < 2; s++) {
            part[mt][s] += __shfl_xor_sync(0xffffffffu, part[mt][s], 1);
            part[mt][s] += __shfl_xor_sync(0xffffffffu, part[mt][s], 2);
        }
    if (tig == 0) {
        #pragma unroll
        for (int mt = 0; mt < 2; mt++) {
            atomicAdd(&L[q0 + wm * 32 + mt * 16 + g], part[mt][0]);
            atomicAdd(&L[q0 + wm * 32 + mt * 16 + 8 + g], part[mt][1]);
        }
    }
}

// ---------------- 4. PV with inline diff, cp.async double-buffered ----------------
__global__ void __launch_bounds__(256, 2) pv_diff() {
    extern __shared__ float sm[];
    float* E1b[2] = { sm,         sm + 4608 };
    float* E2b[2] = { sm + 9216,  sm + 13824 };
    float* Vb[2]  = { sm + 18432, sm + 22656 };
    int tid = threadIdx.x, lane = tid & 31, warp = tid >> 5;
    int g = lane >> 2, tig = lane & 3;
    int wm = warp >> 1, wn = warp & 1;
    int n0 = blockIdx.x * 128, h = blockIdx.y;
    float lam = g_lam;

    const float* E1 = g_E1 + (size_t)h * NSEQ * NSEQ;
    const float* E2 = g_E2 + (size_t)h * NSEQ * NSEQ;
    const float* L1 = g_l1 + (size_t)h * NSEQ;
    const float* L2 = g_l2 + (size_t)h * NSEQ;
    const float* V  = g_v  + (size_t)h * NSEQ * D2;

    // per-thread row reciprocals (rows: wm*32 + mt*16 + {0,8} + g)
    float rl1[2][2], rl2[2][2];
    #pragma unroll
    for (int mt = 0; mt < 2; mt++)
        #pragma unroll
        for (int rr = 0; rr < 2; rr++) {
            int row = n0 + wm * 32 + mt * 16 + rr * 8 + g;
            rl1[mt][rr] = 1.0f / L1[row];
            rl2[mt][rr] = lam / L2[row];
        }

    #pragma unroll
    for (int p = 0; p < 4; p++) {
        int r = (tid >> 3) + p * 32, c = (tid & 7) * 4;
        cp16(E1b[0] + r * 36 + c, &E1[(size_t)(n0 + r) * NSEQ + c]);
        cp16(E2b[0] + r * 36 + c, &E2[(size_t)(n0 + r) * NSEQ + c]);
        int k = (tid >> 5) + p * 8, c4 = (tid & 31) * 4;
        cp16(Vb[0] + k * 132 + c4, &V[(size_t)k * D2 + c4]);
    }
    CP_COMMIT();

    float acc[2][8][4] = {};
    const int NIT = NSEQ / 32;
    for (int i = 0; i < NIT; i++) {
        if (i + 1 < NIT) {
            int kt = (i + 1) * 32, buf = (i + 1) & 1;
            #pragma unroll
            for (int p = 0; p < 4; p++) {
                int r = (tid >> 3) + p * 32, c = (tid & 7) * 4;
                cp16(E1b[buf] + r * 36 + c, &E1[(size_t)(n0 + r) * NSEQ + kt + c]);
                cp16(E2b[buf] + r * 36 + c, &E2[(size_t)(n0 + r) * NSEQ + kt + c]);
                int k = (tid >> 5) + p * 8, c4 = (tid & 31) * 4;
                cp16(Vb[buf] + k * 132 + c4, &V[(size_t)(kt + k) * D2 + c4]);
            }
            CP_COMMIT();
            CP_WAIT1();
        } else {
            CP_WAIT0();
        }
        __syncthreads();
        const float* e1f = E1b[i & 1];
        const float* e2f = E2b[i & 1];
        const float* vf  = Vb[i & 1];
        #pragma unroll
        for (int kc = 0; kc < 4; kc++) {
            unsigned a_[2][4], b_[8][2];
            #pragma unroll
            for (int mt = 0; mt < 2; mt++) {
                int m_ = wm * 32 + mt * 16;
                a_[mt][0] = f2tf(e1f[(m_ + g) * 36 + kc*8 + tig]     * rl1[mt][0] - e2f[(m_ + g) * 36 + kc*8 + tig]     * rl2[mt][0]);
                a_[mt][1] = f2tf(e1f[(m_ + g + 8) * 36 + kc*8 + tig] * rl1[mt][1] - e2f[(m_ + g + 8) * 36 + kc*8 + tig] * rl2[mt][1]);
                a_[mt][2] = f2tf(e1f[(m_ + g) * 36 + kc*8 + tig+4]     * rl1[mt][0] - e2f[(m_ + g) * 36 + kc*8 + tig+4]     * rl2[mt][0]);
                a_[mt][3] = f2tf(e1f[(m_ + g + 8) * 36 + kc*8 + tig+4] * rl1[mt][1] - e2f[(m_ + g + 8) * 36 + kc*8 + tig+4] * rl2[mt][1]);
            }
            #pragma unroll
            for (int nt = 0; nt < 8; nt++) {
                int n_ = wn * 64 + nt * 8 + g;
                b_[nt][0] = f2tf(vf[(kc*8 + tig) * 132 + n_]);
                b_[nt][1] = f2tf(vf[(kc*8 + tig + 4) * 132 + n_]);
            }
            #pragma unroll
            for (int mt = 0; mt < 2; mt++)
                #pragma unroll
                for (int nt = 0; nt < 8; nt++)
                    MMA_TF32(acc[mt][nt], a_[mt], b_[nt]);
        }
        __syncthreads();
    }
    #pragma unroll
    for (int mt = 0; mt < 2; mt++)
        #pragma unroll
        for (int nt = 0; nt < 8; nt++) {
            int row = n0 + wm * 32 + mt * 16 + g;
            int col = wn * 64 + nt * 8 + 2 * tig;
            *(float2*)&g_out2d[(size_t)row * (2*CDIM) + h * D2 + col] =
                make_float2(acc[mt][nt][0], acc[mt][nt][1]);
            *(float2*)&g_out2d[(size_t)(row + 8) * (2*CDIM) + h * D2 + col] =
                make_float2(acc[mt][nt][2], acc[mt][nt][3]);
        }
}

// ---------------- 5. proj: NT tf32, cp.async double-buffered ----------------
__global__ void __launch_bounds__(256, 2) proj_mma(float* __restrict__ out) {
    extern __shared__ float sm[];
    float* Asb[2] = { sm,        sm + 4608 };
    float* Bsb[2] = { sm + 9216, sm + 13824 };
    int tid = threadIdx.x, lane = tid & 31, warp = tid >> 5;
    int g = lane >> 2, tig = lane & 3;
    int wm = warp >> 1, wn = warp & 1;
    int n0 = blockIdx.y * 128, c0 = blockIdx.x * 128;

    #pragma unroll
    for (int p = 0; p < 4; p++) {
        int r = (tid >> 3) + p * 32, c = (tid & 7) * 4;
        cp16(Asb[0] + r * 36 + c, &g_out2d[(size_t)(n0 + r) * (2*CDIM) + c]);
        cp16(Bsb[0] + r * 36 + c, &g_wp[(size_t)(c0 + r) * (2*CDIM) + c]);
    }
    CP_COMMIT();

    float acc[2][8][4] = {};
    const int NIT = (2 * CDIM) / 32;
    for (int i = 0; i < NIT; i++) {
        if (i + 1 < NIT) {
            int kt = (i + 1) * 32, buf = (i + 1) & 1;
            #pragma unroll
            for (int p = 0; p < 4; p++) {
                int r = (tid >> 3) + p * 32, c = (tid & 7) * 4;
                cp16(Asb[buf] + r * 36 + c, &g_out2d[(size_t)(n0 + r) * (2*CDIM) + kt + c]);
                cp16(Bsb[buf] + r * 36 + c, &g_wp[(size_t)(c0 + r) * (2*CDIM) + kt + c]);
            }
            CP_COMMIT();
            CP_WAIT1();
        } else {
            CP_WAIT0();
        }
        __syncthreads();
        const float* A = Asb[i & 1];
        const float* B = Bsb[i & 1];
        #pragma unroll
        for (int kc = 0; kc < 4; kc++) NT_KCHUNK_F(acc, A, B, kc);
        __syncthreads();
    }
    #pragma unroll
    for (int mt = 0; mt < 2; mt++)
        #pragma unroll
        for (int nt = 0; nt < 8; nt++) {
            int row = n0 + wm * 32 + mt * 16 + g;
            int col = c0 + wn * 64 + nt * 8 + 2 * tig;
            *(float2*)&out[(size_t)row * CDIM + col] = make_float2(acc[mt][nt][0], acc[mt][nt][1]);
            *(float2*)&out[(size_t)(row + 8) * CDIM + col] = make_float2(acc[mt][nt][2], acc[mt][nt][3]);
        }
}

// ---------------- launch ----------------
extern "C" void kernel_launch(void* const* d_in, const int* in_sizes, int n_in,
                              void* d_out, int out_size) {
    const float* Wqkv = 0;
    const float* bigs[2] = {0, 0};
    const float* smalls[4] = {0, 0, 0, 0};
    int nbig = 0, nsmall = 0;
    for (int i = 0; i < n_in; i++) {
        const float* p = (const float*)d_in[i];
        if (in_sizes[i] == 6 * CDIM * CDIM) Wqkv = p;
        else if (in_sizes[i] == 2 * CDIM * CDIM) { if (nbig < 2) bigs[nbig++] = p; }
        else if (in_sizes[i] == HD) { if (nsmall < 4) smalls[nsmall++] = p; }
    }
    if (!Wqkv || nbig < 2 || nsmall < 4) {
        bigs[0]   = (const float*)d_in[0];
        Wqkv      = (const float*)d_in[1];
        bigs[1]   = (const float*)d_in[2];
        smalls[0] = (const float*)d_in[3];
        smalls[1] = (const float*)d_in[4];
        smalls[2] = (const float*)d_in[5];
        smalls[3] = (const float*)d_in[6];
    }
    float* out = (float*)d_out;

    const int SMEM_NT = 2 * (4608 + 4608) * 4;                    // 73,728 B
    const int SMEM_PV = (2 * 4608 * 2 + 2 * 4224) * 4;            // 107,520 B
    static int attr_set = 0;
    if (!attr_set) {
        cudaFuncSetAttribute(qkv_mma,    cudaFuncAttributeMaxDynamicSharedMemorySize, SMEM_NT);
        cudaFuncSetAttribute(scores_exp, cudaFuncAttributeMaxDynamicSharedMemorySize, SMEM_NT);
        cudaFuncSetAttribute(pv_diff,    cudaFuncAttributeMaxDynamicSharedMemorySize, SMEM_PV);
        cudaFuncSetAttribute(proj_mma,   cudaFuncAttributeMaxDynamicSharedMemorySize, SMEM_NT);
        attr_set = 1;
    }

    detect_kernel<<<1, 256>>>(bigs[0], bigs[1]);
    route_kernel<<<512, 256>>>(bigs[0], bigs[1]);
    lam_kernel<<<1, 64>>>(smalls[0], smalls[1], smalls[2], smalls[3]);
    zero_l<<<NHEADS * NSEQ / 256, 256>>>();

    qkv_mma<<<dim3(48, 16), 256, SMEM_NT>>>(Wqkv);                // [2048,6144]
    rope_naive<<<dim3(NSEQ, NHEADS), 64>>>();
    scores_exp<<<dim3(16, 16, 2 * NHEADS), 256, SMEM_NT>>>();     // E1/E2 + row sums
    pv_diff<<<dim3(16, NHEADS), 256, SMEM_PV>>>();                // diff inline + PV
    proj_mma<<<dim3(8, 16), 256, SMEM_NT>>>(out);                 // [2048,1024]
}

// round 14
// speedup vs baseline: 1.0897x; 1.0897x over previous
#include <cuda_runtime.h>
#include <math.h>

#define NHEADS 16
#define NSEQ   2048
#define CDIM   1024
#define HD     64
#define D2     128

// ---------------- scratch ----------------
__device__ float g_x[(size_t)NSEQ * CDIM];                 // tf32-rounded x
__device__ float g_wp[(size_t)CDIM * 2 * CDIM];            // tf32-rounded W_proj
__device__ float g_wq[(size_t)6 * CDIM * CDIM];            // tf32-rounded W_qkv
__device__ float g_qkv[(size_t)NSEQ * 6 * CDIM];
__device__ float g_q[(size_t)NHEADS * NSEQ * D2];          // tf32-rounded
__device__ float g_k[(size_t)NHEADS * NSEQ * D2];          // tf32-rounded
__device__ float g_v[(size_t)NHEADS * NSEQ * D2];          // tf32-rounded
__device__ float g_S1[(size_t)NHEADS * NSEQ * NSEQ];       // scores -> P (tf32-rounded)
__device__ float g_S2[(size_t)NHEADS * NSEQ * NSEQ];
__device__ float g_out2d[(size_t)NSEQ * 2 * CDIM];         // tf32-rounded
__device__ float g_lam;
__device__ int   g_use;

// ---------------- tf32 / cp.async helpers ----------------
__device__ __forceinline__ unsigned f2tf(float f) {
    unsigned r;
    asm("cvt.rna.tf32.f32 %0, %1;" : "=r"(r) : "f"(f));
    return r;
}
__device__ __forceinline__ float rtf(float f) { return __uint_as_float(f2tf(f)); }

__device__ __forceinline__ void cp16(float* smem, const float* gmem) {
    unsigned s = (unsigned)__cvta_generic_to_shared(smem);
    asm volatile("cp.async.ca.shared.global [%0], [%1], 16;" :: "r"(s), "l"(gmem));
}
#define CP_COMMIT() asm volatile("cp.async.commit_group;")
#define CP_WAIT1()  asm volatile("cp.async.wait_group 1;")
#define CP_WAIT0()  asm volatile("cp.async.wait_group 0;")

#define MMA_TF32(d, a, b)                                                      \
    asm volatile(                                                              \
        "mma.sync.aligned.m16n8k8.row.col.f32.tf32.tf32.f32 "                  \
        "{%0,%1,%2,%3}, {%4,%5,%6,%7}, {%8,%9}, {%0,%1,%2,%3};"                \
        : "+f"((d)[0]), "+f"((d)[1]), "+f"((d)[2]), "+f"((d)[3])               \
        : "r"((a)[0]), "r"((a)[1]), "r"((a)[2]), "r"((a)[3]),                  \
          "r"((b)[0]), "r"((b)[1]))

// NT k-chunk on pre-rounded fp32 smem (stride 36); bit-cast at gather, no cvt.
#define NT_KCHUNK_R(acc, Af, Bf, kc)                                           \
    do {                                                                       \
        unsigned a_[2][4], b_[8][2];                                           \
        _Pragma("unroll")                                                      \
        for (int mt = 0; mt < 2; mt++) {                                       \
            int m_ = wm * 32 + mt * 16;                                        \
            a_[mt][0] = __float_as_uint((Af)[(m_ + g) * 36 + (kc)*8 + tig]);   \
            a_[mt][1] = __float_as_uint((Af)[(m_ + g + 8) * 36 + (kc)*8 + tig]);\
            a_[mt][2] = __float_as_uint((Af)[(m_ + g) * 36 + (kc)*8 + tig + 4]);\
            a_[mt][3] = __float_as_uint((Af)[(m_ + g + 8) * 36 + (kc)*8 + tig + 4]);\
        }                                                                      \
        _Pragma("unroll")                                                      \
        for (int nt = 0; nt < 8; nt++) {                                       \
            int n_ = wn * 64 + nt * 8 + g;                                     \
            b_[nt][0] = __float_as_uint((Bf)[n_ * 36 + (kc)*8 + tig]);         \
            b_[nt][1] = __float_as_uint((Bf)[n_ * 36 + (kc)*8 + tig + 4]);     \
        }                                                                      \
        _Pragma("unroll")                                                      \
        for (int mt = 0; mt < 2; mt++)                                         \
            _Pragma("unroll")                                                  \
            for (int nt = 0; nt < 8; nt++)                                     \
                MMA_TF32((acc)[mt][nt], a_[mt], b_[nt]);                       \
    } while (0)

// ---------------- input disambiguation ----------------
__global__ void detect_kernel(const float* __restrict__ bigA, const float* __restrict__ bigB) {
    __shared__ float sa[256], sb[256];
    int t = threadIdx.x;
    float a = 0.f, b = 0.f;
    for (int i = t; i < 4096; i += 256) { a += fabsf(bigA[i]); b += fabsf(bigB[i]); }
    sa[t] = a; sb[t] = b;
    __syncthreads();
    for (int s = 128; s > 0; s >>= 1) {
        if (t < s) { sa[t] += sa[t + s]; sb[t] += sb[t + s]; }
        __syncthreads();
    }
    if (t == 0) g_use = (sb[0] > sa[0]) ? 1 : 0;
}

// route + tf32-round x and W_proj
__global__ void route_kernel(const float* __restrict__ bigA, const float* __restrict__ bigB) {
    int u = g_use;
    const float* px = u ? bigB : bigA;
    const float* pw = u ? bigA : bigB;
    size_t n = (size_t)NSEQ * CDIM;
    for (size_t i = (size_t)blockIdx.x * blockDim.x + threadIdx.x; i < n;
         i += (size_t)gridDim.x * blockDim.x) {
        g_x[i]  = rtf(px[i]);
        g_wp[i] = rtf(pw[i]);
    }
}

// tf32-round W_qkv into g_wq
__global__ void wround_kernel(const float* __restrict__ Wqkv) {
    size_t n = (size_t)6 * CDIM * CDIM;
    for (size_t i = (size_t)blockIdx.x * blockDim.x + threadIdx.x; i < n;
         i += (size_t)gridDim.x * blockDim.x)
        g_wq[i] = rtf(Wqkv[i]);
}

__global__ void lam_kernel(const float* __restrict__ s0, const float* __restrict__ s1,
                           const float* __restrict__ s2, const float* __restrict__ s3) {
    __shared__ float sa[64], sb[64];
    int t = threadIdx.x;
    sa[t] = s0[t] * s2[t];
    sb[t] = s1[t] * s3[t];
    __syncthreads();
    for (int s = 32; s > 0; s >>= 1) {
        if (t < s) { sa[t] += sa[t + s]; sb[t] += sb[t + s]; }
        __syncthreads();
    }
    if (t == 0) g_lam = expf(sa[0]) - expf(sb[0]) + 0.2f;
}

// ---------------- 1. qkv: NT tf32, cp.async double-buffered, no cvt ----------------
__global__ void __launch_bounds__(256, 2) qkv_mma() {
    extern __shared__ float sm[];
    float* Asb[2] = { sm,        sm + 4608 };
    float* Bsb[2] = { sm + 9216, sm + 13824 };
    int tid = threadIdx.x, lane = tid & 31, warp = tid >> 5;
    int g = lane >> 2, tig = lane & 3;
    int wm = warp >> 1, wn = warp & 1;
    int n0 = blockIdx.y * 128, d0 = blockIdx.x * 128;

    #pragma unroll
    for (int p = 0; p < 4; p++) {
        int r = (tid >> 3) + p * 32, c = (tid & 7) * 4;
        cp16(Asb[0] + r * 36 + c, &g_x[(size_t)(n0 + r) * CDIM + c]);
        cp16(Bsb[0] + r * 36 + c, &g_wq[(size_t)(d0 + r) * CDIM + c]);
    }
    CP_COMMIT();

    float acc[2][8][4] = {};
    const int NIT = CDIM / 32;
    for (int i = 0; i < NIT; i++) {
        if (i + 1 < NIT) {
            int kt = (i + 1) * 32, buf = (i + 1) & 1;
            #pragma unroll
            for (int p = 0; p < 4; p++) {
                int r = (tid >> 3) + p * 32, c = (tid & 7) * 4;
                cp16(Asb[buf] + r * 36 + c, &g_x[(size_t)(n0 + r) * CDIM + kt + c]);
                cp16(Bsb[buf] + r * 36 + c, &g_wq[(size_t)(d0 + r) * CDIM + kt + c]);
            }
            CP_COMMIT();
            CP_WAIT1();
        } else {
            CP_WAIT0();
        }
        __syncthreads();
        const float* A = Asb[i & 1];
        const float* B = Bsb[i & 1];
        #pragma unroll
        for (int kc = 0; kc < 4; kc++) NT_KCHUNK_R(acc, A, B, kc);
        __syncthreads();
    }
    #pragma unroll
    for (int mt = 0; mt < 2; mt++)
        #pragma unroll
        for (int nt = 0; nt < 8; nt++) {
            int row = n0 + wm * 32 + mt * 16 + g;
            int col = d0 + wn * 64 + nt * 8 + 2 * tig;
            *(float2*)&g_qkv[(size_t)row * (6*CDIM) + col] = make_float2(acc[mt][nt][0], acc[mt][nt][1]);
            *(float2*)&g_qkv[(size_t)(row + 8) * (6*CDIM) + col] = make_float2(acc[mt][nt][2], acc[mt][nt][3]);
        }
}

// ---------------- 2. reorg + RoPE; stores tf32-rounded q/k/v ----------------
__global__ void __launch_bounds__(64) rope_naive() {
    int n = blockIdx.x;
    int h = blockIdx.y;
    int e = threadIdx.x;
    const float* row = g_qkv + (size_t)n * (6 * CDIM);
    int base = h * HD + e;
    float qa = row[0 * CDIM + base];
    float qb = row[1 * CDIM + base];
    float ka = row[2 * CDIM + base];
    float kb = row[3 * CDIM + base];
    float va = row[4 * CDIM + base];
    float vb = row[5 * CDIM + base];

    double invf = exp(-(double)e * (9.210340371976184 / 64.0));
    double th = (double)n * invf;
    float c = (float)cos(th);
    float s = (float)sin(th);

    size_t o = ((size_t)h * NSEQ + n) * D2;
    g_q[o + e]      = rtf(qa * c - qb * s);
    g_q[o + 64 + e] = rtf(qb * c + qa * s);
    g_k[o + e]      = rtf(ka * c - kb * s);
    g_k[o + 64 + e] = rtf(kb * c + ka * s);
    g_v[o + e]      = rtf(va);
    g_v[o + 64 + e] = rtf(vb);
}

// ---------------- 3. scores: batched NT tf32, double-buffered, no cvt ----------------
__global__ void __launch_bounds__(256, 2) scores_mma() {
    extern __shared__ float sm[];
    float* Asb[2] = { sm,        sm + 4608 };
    float* Bsb[2] = { sm + 9216, sm + 13824 };
    int tid = threadIdx.x, lane = tid & 31, warp = tid >> 5;
    int g = lane >> 2, tig = lane & 3;
    int wm = warp >> 1, wn = warp & 1;
    int z = blockIdx.z, h = z >> 1, half = z & 1;
    int q0 = blockIdx.y * 128, k0 = blockIdx.x * 128;

    const float* A = g_q + (size_t)h * NSEQ * D2 + half * 64;
    const float* B = g_k + (size_t)h * NSEQ * D2 + half * 64;
    float* C = (half ? g_S2 : g_S1) + (size_t)h * NSEQ * NSEQ;

    #pragma unroll
    for (int p = 0; p < 4; p++) {
        int r = (tid >> 3) + p * 32, c = (tid & 7) * 4;
        cp16(Asb[0] + r * 36 + c, &A[(size_t)(q0 + r) * D2 + c]);
        cp16(Bsb[0] + r * 36 + c, &B[(size_t)(k0 + r) * D2 + c]);
    }
    CP_COMMIT();

    float acc[2][8][4] = {};
    #pragma unroll
    for (int i = 0; i < 2; i++) {
        if (i == 0) {
            #pragma unroll
            for (int p = 0; p < 4; p++) {
                int r = (tid >> 3) + p * 32, c = (tid & 7) * 4;
                cp16(Asb[1] + r * 36 + c, &A[(size_t)(q0 + r) * D2 + 32 + c]);
                cp16(Bsb[1] + r * 36 + c, &B[(size_t)(k0 + r) * D2 + 32 + c]);
            }
            CP_COMMIT();
            CP_WAIT1();
        } else {
            CP_WAIT0();
        }
        __syncthreads();
        const float* Af = Asb[i];
        const float* Bf = Bsb[i];
        #pragma unroll
        for (int kc = 0; kc < 4; kc++) NT_KCHUNK_R(acc, Af, Bf, kc);
        __syncthreads();
    }
    #pragma unroll
    for (int mt = 0; mt < 2; mt++)
        #pragma unroll
        for (int nt = 0; nt < 8; nt++) {
            int row = q0 + wm * 32 + mt * 16 + g;
            int col = k0 + wn * 64 + nt * 8 + 2 * tig;
            *(float2*)&C[(size_t)row * NSEQ + col] =
                make_float2(acc[mt][nt][0] * 0.125f, acc[mt][nt][1] * 0.125f);
            *(float2*)&C[(size_t)(row + 8) * NSEQ + col] =
                make_float2(acc[mt][nt][2] * 0.125f, acc[mt][nt][3] * 0.125f);
        }
}

// ---------------- 4. softmax diff (R9 validated; stores tf32-rounded P) ----------------
__global__ void __launch_bounds__(256) softmax_diff256() {
    size_t row = blockIdx.x;
    float* s1 = g_S1 + row * NSEQ;
    float* s2 = g_S2 + row * NSEQ;
    int tid = threadIdx.x;
    int lane = tid & 31, warp = tid >> 5;
    __shared__ float wr1[8], wr2[8];

    float v1[8], v2[8];
    float m1 = -1e30f, m2 = -1e30f;
    #pragma unroll
    for (int t = 0; t < 8; t++) {
        v1[t] = s1[tid + t * 256];
        v2[t] = s2[tid + t * 256];
        m1 = fmaxf(m1, v1[t]);
        m2 = fmaxf(m2, v2[t]);
    }
    #pragma unroll
    for (int o = 16; o > 0; o >>= 1) {
        m1 = fmaxf(m1, __shfl_xor_sync(0xffffffffu, m1, o));
        m2 = fmaxf(m2, __shfl_xor_sync(0xffffffffu, m2, o));
    }
    if (lane == 0) { wr1[warp] = m1; wr2[warp] = m2; }
    __syncthreads();
    m1 = wr1[0]; m2 = wr2[0];
    #pragma unroll
    for (int w = 1; w < 8; w++) { m1 = fmaxf(m1, wr1[w]); m2 = fmaxf(m2, wr2[w]); }
    __syncthreads();

    float l1 = 0.f, l2 = 0.f;
    #pragma unroll
    for (int t = 0; t < 8; t++) {
        v1[t] = __expf(v1[t] - m1);
        v2[t] = __expf(v2[t] - m2);
        l1 += v1[t];
        l2 += v2[t];
    }
    #pragma unroll
    for (int o = 16; o > 0; o >>= 1) {
        l1 += __shfl_xor_sync(0xffffffffu, l1, o);
        l2 += __shfl_xor_sync(0xffffffffu, l2, o);
    }
    if (lane == 0) { wr1[warp] = l1; wr2[warp] = l2; }
    __syncthreads();
    l1 = 0.f; l2 = 0.f;
    #pragma unroll
    for (int w = 0; w < 8; w++) { l1 += wr1[w]; l2 += wr2[w]; }

    float r1 = 1.0f / l1;
    float r2 = g_lam / l2;
    #pragma unroll
    for (int t = 0; t < 8; t++)
        s1[tid + t * 256] = rtf(v1[t] * r1 - v2[t] * r2);
}

// ---------------- 5. PV: NN tf32, double-buffered, no cvt ----------------
__global__ void __launch_bounds__(256, 2) pv_mma() {
    extern __shared__ float sm[];
    float* Pb[2] = { sm,        sm + 4608 };   // P: [n][k], stride 36
    float* Vb[2] = { sm + 9216, sm + 13440 };  // V: [k][d], stride 132
    int tid = threadIdx.x, lane = tid & 31, warp = tid >> 5;
    int g = lane >> 2, tig = lane & 3;
    int wm = warp >> 1, wn = warp & 1;
    int n0 = blockIdx.x * 128, h = blockIdx.y;

    const float* P = g_S1 + (size_t)h * NSEQ * NSEQ;
    const float* V = g_v  + (size_t)h * NSEQ * D2;

    #pragma unroll
    for (int p = 0; p < 4; p++) {
        int r = (tid >> 3) + p * 32, c = (tid & 7) * 4;
        cp16(Pb[0] + r * 36 + c, &P[(size_t)(n0 + r) * NSEQ + c]);
        int k = (tid >> 5) + p * 8, c4 = (tid & 31) * 4;
        cp16(Vb[0] + k * 132 + c4, &V[(size_t)k * D2 + c4]);
    }
    CP_COMMIT();

    float acc[2][8][4] = {};
    const int NIT = NSEQ / 32;
    for (int i = 0; i < NIT; i++) {
        if (i + 1 < NIT) {
            int kt = (i + 1) * 32, buf = (i + 1) & 1;
            #pragma unroll
            for (int p = 0; p < 4; p++) {
                int r = (tid >> 3) + p * 32, c = (tid & 7) * 4;
                cp16(Pb[buf] + r * 36 + c, &P[(size_t)(n0 + r) * NSEQ + kt + c]);
                int k = (tid >> 5) + p * 8, c4 = (tid & 31) * 4;
                cp16(Vb[buf] + k * 132 + c4, &V[(size_t)(kt + k) * D2 + c4]);
            }
            CP_COMMIT();
            CP_WAIT1();
        } else {
            CP_WAIT0();
        }
        __syncthreads();
        const float* pf = Pb[i & 1];
        const float* vf = Vb[i & 1];
        #pragma unroll
        for (int kc = 0; kc < 4; kc++) {
            unsigned a_[2][4], b_[8][2];
            #pragma unroll
            for (int mt = 0; mt < 2; mt++) {
                int m_ = wm * 32 + mt * 16;
                a_[mt][0] = __float_as_uint(pf[(m_ + g) * 36 + kc*8 + tig]);
                a_[mt][1] = __float_as_uint(pf[(m_ + g + 8) * 36 + kc*8 + tig]);
                a_[mt][2] = __float_as_uint(pf[(m_ + g) * 36 + kc*8 + tig + 4]);
                a_[mt][3] = __float_as_uint(pf[(m_ + g + 8) * 36 + kc*8 + tig + 4]);
            }
            #pragma unroll
            for (int nt = 0; nt < 8; nt++) {
                int n_ = wn * 64 + nt * 8 + g;
                b_[nt][0] = __float_as_uint(vf[(kc*8 + tig) * 132 + n_]);
                b_[nt][1] = __float_as_uint(vf[(kc*8 + tig + 4) * 132 + n_]);
            }
            #pragma unroll
            for (int mt = 0; mt < 2; mt++)
                #pragma unroll
                for (int nt = 0; nt < 8; nt++)
                    MMA_TF32(acc[mt][nt], a_[mt], b_[nt]);
        }
        __syncthreads();
    }
    #pragma unroll
    for (int mt = 0; mt < 2; mt++)
        #pragma unroll
        for (int nt = 0; nt < 8; nt++) {
            int row = n0 + wm * 32 + mt * 16 + g;
            int col = wn * 64 + nt * 8 + 2 * tig;
            *(float2*)&g_out2d[(size_t)row * (2*CDIM) + h * D2 + col] =
                make_float2(__uint_as_float(f2tf(acc[mt][nt][0])), __uint_as_float(f2tf(acc[mt][nt][1])));
            *(float2*)&g_out2d[(size_t)(row + 8) * (2*CDIM) + h * D2 + col] =
                make_float2(__uint_as_float(f2tf(acc[mt][nt][2])), __uint_as_float(f2tf(acc[mt][nt][3])));
        }
}

// ---------------- 6. proj: NT tf32, double-buffered, no cvt ----------------
__global__ void __launch_bounds__(256, 2) proj_mma(float* __restrict__ out) {
    extern __shared__ float sm[];
    float* Asb[2] = { sm,        sm + 4608 };
    float* Bsb[2] = { sm + 9216, sm + 13824 };
    int tid = threadIdx.x, lane = tid & 31, warp = tid >> 5;
    int g = lane >> 2, tig = lane & 3;
    int wm = warp >> 1, wn = warp & 1;
    int n0 = blockIdx.y * 128, c0 = blockIdx.x * 128;

    #pragma unroll
    for (int p = 0; p < 4; p++) {
        int r = (tid >> 3) + p * 32, c = (tid & 7) * 4;
        cp16(Asb[0] + r * 36 + c, &g_out2d[(size_t)(n0 + r) * (2*CDIM) + c]);
        cp16(Bsb[0] + r * 36 + c, &g_wp[(size_t)(c0 + r) * (2*CDIM) + c]);
    }
    CP_COMMIT();

    float acc[2][8][4] = {};
    const int NIT = (2 * CDIM) / 32;
    for (int i = 0; i < NIT; i++) {
        if (i + 1 < NIT) {
            int kt = (i + 1) * 32, buf = (i + 1) & 1;
            #pragma unroll
            for (int p = 0; p < 4; p++) {
                int r = (tid >> 3) + p * 32, c = (tid & 7) * 4;
                cp16(Asb[buf] + r * 36 + c, &g_out2d[(size_t)(n0 + r) * (2*CDIM) + kt + c]);
                cp16(Bsb[buf] + r * 36 + c, &g_wp[(size_t)(c0 + r) * (2*CDIM) + kt + c]);
            }
            CP_COMMIT();
            CP_WAIT1();
        } else {
            CP_WAIT0();
        }
        __syncthreads();
        const float* A = Asb[i & 1];
        const float* B = Bsb[i & 1];
        #pragma unroll
        for (int kc = 0; kc < 4; kc++) NT_KCHUNK_R(acc, A, B, kc);
        __syncthreads();
    }
    #pragma unroll
    for (int mt = 0; mt < 2; mt++)
        #pragma unroll
        for (int nt = 0; nt < 8; nt++) {
            int row = n0 + wm * 32 + mt * 16 + g;
            int col = c0 + wn * 64 + nt * 8 + 2 * tig;
            *(float2*)&out[(size_t)row * CDIM + col] = make_float2(acc[mt][nt][0], acc[mt][nt][1]);
            *(float2*)&out[(size_t)(row + 8) * CDIM + col] = make_float2(acc[mt][nt][2], acc[mt][nt][3]);
        }
}

// ---------------- launch ----------------
extern "C" void kernel_launch(void* const* d_in, const int* in_sizes, int n_in,
                              void* d_out, int out_size) {
    const float* Wqkv = 0;
    const float* bigs[2] = {0, 0};
    const float* smalls[4] = {0, 0, 0, 0};
    int nbig = 0, nsmall = 0;
    for (int i = 0; i < n_in; i++) {
        const float* p = (const float*)d_in[i];
        if (in_sizes[i] == 6 * CDIM * CDIM) Wqkv = p;
        else if (in_sizes[i] == 2 * CDIM * CDIM) { if (nbig < 2) bigs[nbig++] = p; }
        else if (in_sizes[i] == HD) { if (nsmall < 4) smalls[nsmall++] = p; }
    }
    if (!Wqkv || nbig < 2 || nsmall < 4) {
        bigs[0]   = (const float*)d_in[0];
        Wqkv      = (const float*)d_in[1];
        bigs[1]   = (const float*)d_in[2];
        smalls[0] = (const float*)d_in[3];
        smalls[1] = (const float*)d_in[4];
        smalls[2] = (const float*)d_in[5];
        smalls[3] = (const float*)d_in[6];
    }
    float* out = (float*)d_out;

    const int SMEM_NT = 2 * (4608 + 4608) * 4;          // 73,728 B
    const int SMEM_PV = (2 * 4608 + 2 * 4224) * 4;      // 70,656 B
    static int attr_set = 0;
    if (!attr_set) {
        cudaFuncSetAttribute(qkv_mma,    cudaFuncAttributeMaxDynamicSharedMemorySize, SMEM_NT);
        cudaFuncSetAttribute(scores_mma, cudaFuncAttributeMaxDynamicSharedMemorySize, SMEM_NT);
        cudaFuncSetAttribute(pv_mma,     cudaFuncAttributeMaxDynamicSharedMemorySize, SMEM_PV);
        cudaFuncSetAttribute(proj_mma,   cudaFuncAttributeMaxDynamicSharedMemorySize, SMEM_NT);
        attr_set = 1;
    }

    detect_kernel<<<1, 256>>>(bigs[0], bigs[1]);
    route_kernel<<<512, 256>>>(bigs[0], bigs[1]);
    wround_kernel<<<512, 256>>>(Wqkv);
    lam_kernel<<<1, 64>>>(smalls[0], smalls[1], smalls[2], smalls[3]);

    qkv_mma<<<dim3(48, 16), 256, SMEM_NT>>>();                    // [2048,6144]
    rope_naive<<<dim3(NSEQ, NHEADS), 64>>>();
    scores_mma<<<dim3(16, 16, 2 * NHEADS), 256, SMEM_NT>>>();     // S1/S2
    softmax_diff256<<<NHEADS * NSEQ, 256>>>();                    // P -> g_S1
    pv_mma<<<dim3(16, NHEADS), 256, SMEM_PV>>>();                 // [2048,128] per head
    proj_mma<<<dim3(8, 16), 256, SMEM_NT>>>(out);                 // [2048,1024]
}